// round 4
// baseline (speedup 1.0000x reference)
#include <cuda_runtime.h>
#include <cstdint>

// Problem constants
#define N_PTS  262144
#define CHANS  96
#define KOFF   27

#define TILE_M   128
#define THREADS  256
#define A_STRIDE 100   // words; conflict-free for the mma A-fragment pattern
#define W_STRIDE 104   // words; 104%32=8 -> conflict-free for B-fragment pattern

// Scratch for the intermediate activation x = prelu(conv1(feats)) : [N, CH] fp32
__device__ float g_x[(size_t)N_PTS * CHANS];

__device__ __forceinline__ uint32_t f2tf32(float f) {
    uint32_t u;
    asm("cvt.rna.tf32.f32 %0, %1;" : "=r"(u) : "f"(f));
    return u;
}

// One sparse-conv layer: out = act( bias + sum_k mask * gather(src, idx_k) @ W_k  [+ residual] )
// act = PReLU(alpha). residual == nullptr for layer 1.
extern "C" __global__ void __launch_bounds__(THREADS, 2)
sparse_conv_kernel(const float* __restrict__ src,            // gather source [N, CH]
                   const int* __restrict__ nbr,              // [K, N]
                   const int* __restrict__ mask,             // [K, N] bool promoted to int32
                   const float* __restrict__ W,              // [K, CH, CH]
                   const float* __restrict__ bias,           // [CH]
                   const float* __restrict__ alpha,          // [1]
                   const float* __restrict__ residual,       // [N, CH] or nullptr
                   float* __restrict__ out)                  // [N, CH]
{
    extern __shared__ uint32_t smem[];
    uint32_t* As   = smem;                         // TILE_M * A_STRIDE words (tf32 bits)
    uint32_t* Ws   = As + TILE_M * A_STRIDE;       // CHANS * W_STRIDE words (tf32 bits)
    int*      sIdx = (int*)(Ws + CHANS * W_STRIDE);// TILE_M

    const int tid  = threadIdx.x;
    const int lane = tid & 31;
    const int wid  = tid >> 5;
    const int tb   = blockIdx.x * TILE_M;

    // 8 warps: 4 (M) x 2 (N). Warp tile: 32 rows x 48 cols.
    const int row_base = (wid & 3) * 32;
    const int col_base = (wid >> 2) * 48;

    float acc[2][6][4];
#pragma unroll
    for (int mt = 0; mt < 2; mt++)
#pragma unroll
        for (int nt = 0; nt < 6; nt++)
#pragma unroll
            for (int i = 0; i < 4; i++) acc[mt][nt][i] = 0.f;

    for (int k = 0; k < KOFF; k++) {
        // ---- stage neighbor indices (mask folded in as -1) ----
        if (tid < TILE_M) {
            size_t o = (size_t)k * N_PTS + tb + tid;
            int i = nbr[o];
            sIdx[tid] = (mask[o] != 0) ? i : -1;
        }
        __syncthreads();

        // ---- gather A tile: 128 rows x 96 floats (24 float4 per row) ----
#pragma unroll
        for (int it = 0; it < (TILE_M * 24) / THREADS; it++) {
            int j  = tid + it * THREADS;
            int r  = j / 24;
            int c4 = j - r * 24;
            int s  = sIdx[r];
            uint4 v = make_uint4(0u, 0u, 0u, 0u);
            if (s >= 0) {
                const float4 f = *(const float4*)(src + (size_t)s * CHANS + c4 * 4);
                v.x = f2tf32(f.x); v.y = f2tf32(f.y); v.z = f2tf32(f.z); v.w = f2tf32(f.w);
            }
            *(uint4*)(As + r * A_STRIDE + c4 * 4) = v;
        }

        // ---- stage W[k]: 96x96 floats ----
        {
            const float* Wk = W + (size_t)k * CHANS * CHANS;
#pragma unroll
            for (int it = 0; it < (CHANS * 24) / THREADS; it++) {
                int j  = tid + it * THREADS;
                int r  = j / 24;
                int c4 = j - r * 24;
                const float4 f = *(const float4*)(Wk + r * CHANS + c4 * 4);
                uint4 v;
                v.x = f2tf32(f.x); v.y = f2tf32(f.y); v.z = f2tf32(f.z); v.w = f2tf32(f.w);
                *(uint4*)(Ws + r * W_STRIDE + c4 * 4) = v;
            }
        }
        __syncthreads();

        // ---- accumulate: D += A_tile @ W_k  via m16n8k8 tf32 ----
#pragma unroll
        for (int kk = 0; kk < CHANS / 8; kk++) {
            uint32_t bfrag[6][2];
#pragma unroll
            for (int nt = 0; nt < 6; nt++) {
                int c0 = kk * 8 + (lane & 3);
                int j  = col_base + nt * 8 + (lane >> 2);
                bfrag[nt][0] = Ws[c0 * W_STRIDE + j];
                bfrag[nt][1] = Ws[(c0 + 4) * W_STRIDE + j];
            }
#pragma unroll
            for (int mt = 0; mt < 2; mt++) {
                int r = row_base + mt * 16 + (lane >> 2);
                int c = kk * 8 + (lane & 3);
                uint32_t a0 = As[r * A_STRIDE + c];
                uint32_t a1 = As[(r + 8) * A_STRIDE + c];
                uint32_t a2 = As[r * A_STRIDE + c + 4];
                uint32_t a3 = As[(r + 8) * A_STRIDE + c + 4];
#pragma unroll
                for (int nt = 0; nt < 6; nt++) {
                    asm volatile(
                        "mma.sync.aligned.m16n8k8.row.col.f32.tf32.tf32.f32 "
                        "{%0,%1,%2,%3}, {%4,%5,%6,%7}, {%8,%9}, {%0,%1,%2,%3};"
                        : "+f"(acc[mt][nt][0]), "+f"(acc[mt][nt][1]),
                          "+f"(acc[mt][nt][2]), "+f"(acc[mt][nt][3])
                        : "r"(a0), "r"(a1), "r"(a2), "r"(a3),
                          "r"(bfrag[nt][0]), "r"(bfrag[nt][1]));
                }
            }
        }
        __syncthreads();
    }

    // ---- epilogue: bias (+ residual) + PReLU, write out ----
    const float a = alpha[0];
#pragma unroll
    for (int mt = 0; mt < 2; mt++) {
        int r0 = tb + row_base + mt * 16 + (lane >> 2);
#pragma unroll
        for (int nt = 0; nt < 6; nt++) {
            int c0 = col_base + nt * 8 + (lane & 3) * 2;
            float b0 = bias[c0], b1 = bias[c0 + 1];
            float v0 = acc[mt][nt][0] + b0;
            float v1 = acc[mt][nt][1] + b1;
            float v2 = acc[mt][nt][2] + b0;
            float v3 = acc[mt][nt][3] + b1;
            if (residual) {
                v0 += residual[(size_t)r0 * CHANS + c0];
                v1 += residual[(size_t)r0 * CHANS + c0 + 1];
                v2 += residual[(size_t)(r0 + 8) * CHANS + c0];
                v3 += residual[(size_t)(r0 + 8) * CHANS + c0 + 1];
            }
            v0 = v0 > 0.f ? v0 : a * v0;
            v1 = v1 > 0.f ? v1 : a * v1;
            v2 = v2 > 0.f ? v2 : a * v2;
            v3 = v3 > 0.f ? v3 : a * v3;
            *(float2*)(out + (size_t)r0 * CHANS + c0)       = make_float2(v0, v1);
            *(float2*)(out + (size_t)(r0 + 8) * CHANS + c0) = make_float2(v2, v3);
        }
    }
}

static const int SMEM_BYTES = (TILE_M * A_STRIDE + CHANS * W_STRIDE) * 4 + TILE_M * 4;

extern "C" void kernel_launch(void* const* d_in, const int* in_sizes, int n_in,
                              void* d_out, int out_size) {
    const float* feats = (const float*)d_in[0];
    const int*   nbr   = (const int*)d_in[1];
    const int*   msk   = (const int*)d_in[2];   // bool promoted to int32 on the wire
    const float* W1    = (const float*)d_in[3];
    const float* b1    = (const float*)d_in[4];
    const float* a1    = (const float*)d_in[5];
    const float* W2    = (const float*)d_in[6];
    const float* b2    = (const float*)d_in[7];
    const float* a2    = (const float*)d_in[8];
    float*       out   = (float*)d_out;

    float* xbuf = nullptr;
    cudaGetSymbolAddress((void**)&xbuf, g_x);  // host-side query; capture-safe

    cudaFuncSetAttribute(sparse_conv_kernel,
                         cudaFuncAttributeMaxDynamicSharedMemorySize, SMEM_BYTES);

    dim3 grid(N_PTS / TILE_M);
    // layer 1: x = prelu(conv(feats, W1) + b1)
    sparse_conv_kernel<<<grid, THREADS, SMEM_BYTES>>>(
        feats, nbr, msk, W1, b1, a1, /*residual=*/nullptr, xbuf);
    // layer 2: out = prelu(conv(x, W2) + b2 + feats)
    sparse_conv_kernel<<<grid, THREADS, SMEM_BYTES>>>(
        xbuf, nbr, msk, W2, b2, a2, /*residual=*/feats, out);
}

// round 6
// speedup vs baseline: 1.2672x; 1.2672x over previous
#include <cuda_runtime.h>
#include <cstdint>

// Problem constants
#define N_PTS  262144
#define CHANS  96
#define KOFF   27

#define TILE_M   128
#define THREADS  256
#define A_STRIDE 100   // words; conflict-free for the mma A-fragment pattern
#define W_STRIDE 104   // words; conflict-free for the mma B-fragment pattern
#define STAGE_WORDS (TILE_M * A_STRIDE + CHANS * W_STRIDE)   // 22784 words per stage

// Scratch for the intermediate activation x = prelu(conv1(feats)) : [N, CH] fp32
__device__ float g_x[(size_t)N_PTS * CHANS];

__device__ __forceinline__ void cp16(uint32_t dst, const void* src, int sz) {
    // 16B global->shared async copy; sz=0 => full zero-fill (mask folding)
    asm volatile("cp.async.cg.shared.global [%0], [%1], 16, %2;"
                 :: "r"(dst), "l"(src), "r"(sz));
}
__device__ __forceinline__ void cp_commit() { asm volatile("cp.async.commit_group;"); }
__device__ __forceinline__ void cp_wait1()  { asm volatile("cp.async.wait_group 1;"); }

// Issue the async gather of A-tile (mask-predicated) and W[k] into stage buffer.
// Raw fp32 bits are staged; mma.tf32 truncates mantissa in hardware (no cvt needed).
__device__ __forceinline__ void issue_stage(
    int k, int stage, int tb, int tid,
    const float* __restrict__ src, const int* __restrict__ nbr,
    const int* __restrict__ mask, const float* __restrict__ W,
    uint32_t smem_base)
{
    uint32_t As  = smem_base + (uint32_t)stage * STAGE_WORDS * 4;
    uint32_t Wsm = As + TILE_M * A_STRIDE * 4;

    // ---- A tile: 128 rows x 24 float4. Thread -> row tid>>1, half-row (12 x 16B). ----
    const int r0 = tid >> 1;
    const int h  = tid & 1;            // which half of the row (c4 base = h*12)
    const size_t o = (size_t)k * N_PTS + tb + r0;
    const int idx = nbr[o];
    const int m   = mask[o];
    const int sz  = m ? 16 : 0;
    const float* srow = src + (size_t)(m ? idx : 0) * CHANS + h * 48;
    uint32_t arow = As + (uint32_t)(r0 * A_STRIDE + h * 48) * 4;
#pragma unroll
    for (int i = 0; i < 12; i++)
        cp16(arow + i * 16, srow + i * 4, sz);

    // ---- W[k]: 96 rows x 24 float4, fully coalesced. 9 x 16B per thread. ----
    const float* Wk = W + (size_t)k * CHANS * CHANS;
#pragma unroll
    for (int it = 0; it < 9; it++) {
        int j  = tid + it * THREADS;
        int r  = j / 24;
        int c4 = j - r * 24;
        cp16(Wsm + (uint32_t)(r * W_STRIDE + c4 * 4) * 4, Wk + r * CHANS + c4 * 4, 16);
    }
}

// One sparse-conv layer: out = prelu( bias + sum_k mask * gather(src, idx_k) @ W_k [+ residual] )
extern "C" __global__ void __launch_bounds__(THREADS, 1)
sparse_conv_kernel(const float* __restrict__ src,
                   const int* __restrict__ nbr,              // [K, N]
                   const int* __restrict__ mask,             // [K, N] bool->int32
                   const float* __restrict__ W,              // [K, CH, CH]
                   const float* __restrict__ bias,           // [CH]
                   const float* __restrict__ alpha,          // [1]
                   const float* __restrict__ residual,       // [N, CH] or nullptr
                   float* __restrict__ out)                  // [N, CH]
{
    extern __shared__ uint32_t smem[];
    const uint32_t smem_base = (uint32_t)__cvta_generic_to_shared(smem);

    const int tid  = threadIdx.x;
    const int lane = tid & 31;
    const int wid  = tid >> 5;
    const int tb   = blockIdx.x * TILE_M;

    // 8 warps: 4 (M) x 2 (N). Warp tile: 32 rows x 48 cols.
    const int row_base = (wid & 3) * 32;
    const int col_base = (wid >> 2) * 48;

    float acc[2][6][4];
#pragma unroll
    for (int mt = 0; mt < 2; mt++)
#pragma unroll
        for (int nt = 0; nt < 6; nt++)
#pragma unroll
            for (int i = 0; i < 4; i++) acc[mt][nt][i] = 0.f;

    // ---- prologue: start gather for k=0 ----
    issue_stage(0, 0, tb, tid, src, nbr, mask, W, smem_base);
    cp_commit();

    for (int k = 0; k < KOFF; k++) {
        const int s = k & 1;
        // issue next stage (buffer s^1 was last read at k-1, protected by that
        // iteration's trailing __syncthreads)
        if (k + 1 < KOFF)
            issue_stage(k + 1, s ^ 1, tb, tid, src, nbr, mask, W, smem_base);
        cp_commit();           // empty group on last iter keeps wait-count uniform
        cp_wait1();            // stage k's copies complete (this thread)
        __syncthreads();       // all threads' copies for stage k visible

        const uint32_t* As = smem + (size_t)s * STAGE_WORDS;
        const uint32_t* Ws = As + TILE_M * A_STRIDE;

#pragma unroll
        for (int kk = 0; kk < CHANS / 8; kk++) {
            uint32_t bfrag[6][2];
#pragma unroll
            for (int nt = 0; nt < 6; nt++) {
                int c0 = kk * 8 + (lane & 3);
                int j  = col_base + nt * 8 + (lane >> 2);
                bfrag[nt][0] = Ws[c0 * W_STRIDE + j];
                bfrag[nt][1] = Ws[(c0 + 4) * W_STRIDE + j];
            }
#pragma unroll
            for (int mt = 0; mt < 2; mt++) {
                int r = row_base + mt * 16 + (lane >> 2);
                int c = kk * 8 + (lane & 3);
                uint32_t a0 = As[r * A_STRIDE + c];
                uint32_t a1 = As[(r + 8) * A_STRIDE + c];
                uint32_t a2 = As[r * A_STRIDE + c + 4];
                uint32_t a3 = As[(r + 8) * A_STRIDE + c + 4];
#pragma unroll
                for (int nt = 0; nt < 6; nt++) {
                    asm volatile(
                        "mma.sync.aligned.m16n8k8.row.col.f32.tf32.tf32.f32 "
                        "{%0,%1,%2,%3}, {%4,%5,%6,%7}, {%8,%9}, {%0,%1,%2,%3};"
                        : "+f"(acc[mt][nt][0]), "+f"(acc[mt][nt][1]),
                          "+f"(acc[mt][nt][2]), "+f"(acc[mt][nt][3])
                        : "r"(a0), "r"(a1), "r"(a2), "r"(a3),
                          "r"(bfrag[nt][0]), "r"(bfrag[nt][1]));
                }
            }
        }
        __syncthreads();       // all warps done reading stage s before k+2 overwrites it
    }

    // ---- epilogue: bias (+ residual) + PReLU, write out ----
    const float a = alpha[0];
#pragma unroll
    for (int mt = 0; mt < 2; mt++) {
        int r0 = tb + row_base + mt * 16 + (lane >> 2);
#pragma unroll
        for (int nt = 0; nt < 6; nt++) {
            int c0 = col_base + nt * 8 + (lane & 3) * 2;
            float b0 = bias[c0], b1 = bias[c0 + 1];
            float v0 = acc[mt][nt][0] + b0;
            float v1 = acc[mt][nt][1] + b1;
            float v2 = acc[mt][nt][2] + b0;
            float v3 = acc[mt][nt][3] + b1;
            if (residual) {
                v0 += residual[(size_t)r0 * CHANS + c0];
                v1 += residual[(size_t)r0 * CHANS + c0 + 1];
                v2 += residual[(size_t)(r0 + 8) * CHANS + c0];
                v3 += residual[(size_t)(r0 + 8) * CHANS + c0 + 1];
            }
            v0 = v0 > 0.f ? v0 : a * v0;
            v1 = v1 > 0.f ? v1 : a * v1;
            v2 = v2 > 0.f ? v2 : a * v2;
            v3 = v3 > 0.f ? v3 : a * v3;
            *(float2*)(out + (size_t)r0 * CHANS + c0)       = make_float2(v0, v1);
            *(float2*)(out + (size_t)(r0 + 8) * CHANS + c0) = make_float2(v2, v3);
        }
    }
}

static const int SMEM_BYTES = STAGE_WORDS * 2 * 4;   // 182,272 B (double-buffered)

extern "C" void kernel_launch(void* const* d_in, const int* in_sizes, int n_in,
                              void* d_out, int out_size) {
    const float* feats = (const float*)d_in[0];
    const int*   nbr   = (const int*)d_in[1];
    const int*   msk   = (const int*)d_in[2];   // bool promoted to int32 on the wire
    const float* W1    = (const float*)d_in[3];
    const float* b1    = (const float*)d_in[4];
    const float* a1    = (const float*)d_in[5];
    const float* W2    = (const float*)d_in[6];
    const float* b2    = (const float*)d_in[7];
    const float* a2    = (const float*)d_in[8];
    float*       out   = (float*)d_out;

    float* xbuf = nullptr;
    cudaGetSymbolAddress((void**)&xbuf, g_x);  // host-side query; capture-safe

    cudaFuncSetAttribute(sparse_conv_kernel,
                         cudaFuncAttributeMaxDynamicSharedMemorySize, SMEM_BYTES);

    dim3 grid(N_PTS / TILE_M);
    // layer 1: x = prelu(conv(feats, W1) + b1)
    sparse_conv_kernel<<<grid, THREADS, SMEM_BYTES>>>(
        feats, nbr, msk, W1, b1, a1, /*residual=*/nullptr, xbuf);
    // layer 2: out = prelu(conv(x, W2) + b2 + feats)
    sparse_conv_kernel<<<grid, THREADS, SMEM_BYTES>>>(
        xbuf, nbr, msk, W2, b2, a2, /*residual=*/feats, out);
}

// round 7
// speedup vs baseline: 1.3786x; 1.0879x over previous
#include <cuda_runtime.h>
#include <cstdint>

// Problem constants
#define N_PTS  262144
#define CHANS  96
#define KOFF   27

#define TILE_M   128
#define THREADS  256
#define A_STRIDE 100   // words; conflict-free for the mma A-fragment pattern (400B, 16B-mult)
#define W_STRIDE 104   // words; conflict-free for the mma B-fragment pattern (416B, 16B-mult)
#define STAGE_WORDS (TILE_M * A_STRIDE + CHANS * W_STRIDE)   // 22784 words per stage

// Scratch for the intermediate activation x = prelu(conv1(feats)) : [N, CH] fp32
__device__ float g_x[(size_t)N_PTS * CHANS];

// ---- async-bulk + mbarrier primitives ----
__device__ __forceinline__ void cp_bulk(uint32_t dst, const void* src, uint32_t bytes,
                                        uint32_t mbar) {
    asm volatile("cp.async.bulk.shared::cta.global.mbarrier::complete_tx::bytes "
                 "[%0], [%1], %2, [%3];"
                 :: "r"(dst), "l"(src), "r"(bytes), "r"(mbar) : "memory");
}
__device__ __forceinline__ void mbar_init(uint32_t mbar, uint32_t cnt) {
    asm volatile("mbarrier.init.shared.b64 [%0], %1;" :: "r"(mbar), "r"(cnt) : "memory");
}
__device__ __forceinline__ void mbar_arrive_tx(uint32_t mbar, uint32_t bytes) {
    asm volatile("mbarrier.arrive.expect_tx.shared.b64 _, [%0], %1;"
                 :: "r"(mbar), "r"(bytes) : "memory");
}
__device__ __forceinline__ void mbar_wait(uint32_t mbar, uint32_t parity) {
    uint32_t done;
    asm volatile("{\n\t.reg .pred p;\n\t"
                 "mbarrier.try_wait.parity.acquire.cta.shared::cta.b64 p, [%1], %2;\n\t"
                 "selp.b32 %0, 1, 0, p;\n\t}"
                 : "=r"(done) : "r"(mbar), "r"(parity) : "memory");
    while (!done) {
        asm volatile("{\n\t.reg .pred p;\n\t"
                     "mbarrier.try_wait.parity.acquire.cta.shared::cta.b64 p, [%1], %2, 0x989680;\n\t"
                     "selp.b32 %0, 1, 0, p;\n\t}"
                     : "=r"(done) : "r"(mbar), "r"(parity) : "memory");
    }
}

// Issue stage k into buffer `stage`: one 384B bulk copy per valid A row and per W row.
// Masked A rows are zero-filled with STS.128 (visibility via the per-k __syncthreads).
__device__ __forceinline__ void issue_stage(
    int k, int stage, int tb, int tid,
    const float* __restrict__ src, const int* __restrict__ nbr,
    const int* __restrict__ mask, const float* __restrict__ W,
    uint32_t smem_base, uint32_t* smem_generic)
{
    const uint32_t As   = smem_base + (uint32_t)stage * STAGE_WORDS * 4;
    const uint32_t Wsm  = As + TILE_M * A_STRIDE * 4;
    const uint32_t mbar = smem_base + 2u * STAGE_WORDS * 4 + (uint32_t)stage * 8;

    if (tid < TILE_M) {
        // ---- A rows: warps 0-3, one row per thread ----
        const size_t o = (size_t)k * N_PTS + tb + tid;
        const int idx  = nbr[o];
        const int m    = mask[o];
        const unsigned bal = __ballot_sync(0xffffffffu, m != 0);
        if ((tid & 31) == 0)
            mbar_arrive_tx(mbar, __popc(bal) * 384u);
        const uint32_t dst = As + (uint32_t)tid * A_STRIDE * 4;
        if (m) {
            cp_bulk(dst, src + (size_t)idx * CHANS, 384u, mbar);
        } else {
            uint4* zr = (uint4*)((char*)smem_generic +
                                 ((size_t)stage * STAGE_WORDS + (size_t)tid * A_STRIDE) * 4);
#pragma unroll
            for (int i = 0; i < 24; i++) zr[i] = make_uint4(0u, 0u, 0u, 0u);
        }
    } else {
        // ---- W rows: warps 4-7, thread 128+i -> W row i (i < 96) ----
        const int i = tid - TILE_M;
        const unsigned act = __ballot_sync(0xffffffffu, i < CHANS);
        if ((tid & 31) == 0)
            mbar_arrive_tx(mbar, __popc(act) * 384u);
        if (i < CHANS)
            cp_bulk(Wsm + (uint32_t)i * W_STRIDE * 4,
                    W + (size_t)k * CHANS * CHANS + (size_t)i * CHANS, 384u, mbar);
    }
}

// One sparse-conv layer: out = prelu( bias + sum_k mask * gather(src, idx_k) @ W_k [+ residual] )
extern "C" __global__ void __launch_bounds__(THREADS, 1)
sparse_conv_kernel(const float* __restrict__ src,
                   const int* __restrict__ nbr,              // [K, N]
                   const int* __restrict__ mask,             // [K, N] bool->int32
                   const float* __restrict__ W,              // [K, CH, CH]
                   const float* __restrict__ bias,           // [CH]
                   const float* __restrict__ alpha,          // [1]
                   const float* __restrict__ residual,       // [N, CH] or nullptr
                   float* __restrict__ out)                  // [N, CH]
{
    extern __shared__ uint32_t smem[];
    const uint32_t smem_base = (uint32_t)__cvta_generic_to_shared(smem);

    const int tid  = threadIdx.x;
    const int lane = tid & 31;
    const int wid  = tid >> 5;
    const int tb   = blockIdx.x * TILE_M;

    // 8 warps: 4 (M) x 2 (N). Warp tile: 32 rows x 48 cols.
    const int row_base = (wid & 3) * 32;
    const int col_base = (wid >> 2) * 48;

    float acc[2][6][4];
#pragma unroll
    for (int mt = 0; mt < 2; mt++)
#pragma unroll
        for (int nt = 0; nt < 6; nt++)
#pragma unroll
            for (int i = 0; i < 4; i++) acc[mt][nt][i] = 0.f;

    // ---- init mbarriers (count = 8 warp-arrivals per stage use) ----
    if (tid == 0) {
        mbar_init(smem_base + 2u * STAGE_WORDS * 4 + 0, 8);
        mbar_init(smem_base + 2u * STAGE_WORDS * 4 + 8, 8);
    }
    __syncthreads();

    // ---- prologue: start gather for k=0 ----
    issue_stage(0, 0, tb, tid, src, nbr, mask, W, smem_base, smem);

    for (int k = 0; k < KOFF; k++) {
        const int s = k & 1;
        // issue next stage (buffer s^1: last read finished at iteration k-1's
        // trailing __syncthreads; its mbar phase completed at the k-1 wait)
        if (k + 1 < KOFF)
            issue_stage(k + 1, s ^ 1, tb, tid, src, nbr, mask, W, smem_base, smem);

        // wait for stage k's bulk data (parity = use count & 1), then barrier for
        // the generic-proxy STS zero rows issued by other warps.
        mbar_wait(smem_base + 2u * STAGE_WORDS * 4 + (uint32_t)s * 8, (k >> 1) & 1);
        __syncthreads();

        const uint32_t* As = smem + (size_t)s * STAGE_WORDS;
        const uint32_t* Ws = As + TILE_M * A_STRIDE;

#pragma unroll
        for (int kk = 0; kk < CHANS / 8; kk++) {
            uint32_t bfrag[6][2];
#pragma unroll
            for (int nt = 0; nt < 6; nt++) {
                int c0 = kk * 8 + (lane & 3);
                int j  = col_base + nt * 8 + (lane >> 2);
                bfrag[nt][0] = Ws[c0 * W_STRIDE + j];
                bfrag[nt][1] = Ws[(c0 + 4) * W_STRIDE + j];
            }
#pragma unroll
            for (int mt = 0; mt < 2; mt++) {
                int r = row_base + mt * 16 + (lane >> 2);
                int c = kk * 8 + (lane & 3);
                uint32_t a0 = As[r * A_STRIDE + c];
                uint32_t a1 = As[(r + 8) * A_STRIDE + c];
                uint32_t a2 = As[r * A_STRIDE + c + 4];
                uint32_t a3 = As[(r + 8) * A_STRIDE + c + 4];
#pragma unroll
                for (int nt = 0; nt < 6; nt++) {
                    asm volatile(
                        "mma.sync.aligned.m16n8k8.row.col.f32.tf32.tf32.f32 "
                        "{%0,%1,%2,%3}, {%4,%5,%6,%7}, {%8,%9}, {%0,%1,%2,%3};"
                        : "+f"(acc[mt][nt][0]), "+f"(acc[mt][nt][1]),
                          "+f"(acc[mt][nt][2]), "+f"(acc[mt][nt][3])
                        : "r"(a0), "r"(a1), "r"(a2), "r"(a3),
                          "r"(bfrag[nt][0]), "r"(bfrag[nt][1]));
                }
            }
        }
        __syncthreads();   // all warps done reading stage s before k+2 overwrites it
    }

    // ---- epilogue: bias (+ residual) + PReLU, write out ----
    const float a = alpha[0];
#pragma unroll
    for (int mt = 0; mt < 2; mt++) {
        int r0 = tb + row_base + mt * 16 + (lane >> 2);
#pragma unroll
        for (int nt = 0; nt < 6; nt++) {
            int c0 = col_base + nt * 8 + (lane & 3) * 2;
            float b0 = bias[c0], b1 = bias[c0 + 1];
            float v0 = acc[mt][nt][0] + b0;
            float v1 = acc[mt][nt][1] + b1;
            float v2 = acc[mt][nt][2] + b0;
            float v3 = acc[mt][nt][3] + b1;
            if (residual) {
                v0 += residual[(size_t)r0 * CHANS + c0];
                v1 += residual[(size_t)r0 * CHANS + c0 + 1];
                v2 += residual[(size_t)(r0 + 8) * CHANS + c0];
                v3 += residual[(size_t)(r0 + 8) * CHANS + c0 + 1];
            }
            v0 = v0 > 0.f ? v0 : a * v0;
            v1 = v1 > 0.f ? v1 : a * v1;
            v2 = v2 > 0.f ? v2 : a * v2;
            v3 = v3 > 0.f ? v3 : a * v3;
            *(float2*)(out + (size_t)r0 * CHANS + c0)       = make_float2(v0, v1);
            *(float2*)(out + (size_t)(r0 + 8) * CHANS + c0) = make_float2(v2, v3);
        }
    }
}

static const int SMEM_BYTES = STAGE_WORDS * 2 * 4 + 16;   // stages + 2 mbarriers

extern "C" void kernel_launch(void* const* d_in, const int* in_sizes, int n_in,
                              void* d_out, int out_size) {
    const float* feats = (const float*)d_in[0];
    const int*   nbr   = (const int*)d_in[1];
    const int*   msk   = (const int*)d_in[2];   // bool promoted to int32 on the wire
    const float* W1    = (const float*)d_in[3];
    const float* b1    = (const float*)d_in[4];
    const float* a1    = (const float*)d_in[5];
    const float* W2    = (const float*)d_in[6];
    const float* b2    = (const float*)d_in[7];
    const float* a2    = (const float*)d_in[8];
    float*       out   = (float*)d_out;

    float* xbuf = nullptr;
    cudaGetSymbolAddress((void**)&xbuf, g_x);  // host-side query; capture-safe

    cudaFuncSetAttribute(sparse_conv_kernel,
                         cudaFuncAttributeMaxDynamicSharedMemorySize, SMEM_BYTES);

    dim3 grid(N_PTS / TILE_M);
    // layer 1: x = prelu(conv(feats, W1) + b1)
    sparse_conv_kernel<<<grid, THREADS, SMEM_BYTES>>>(
        feats, nbr, msk, W1, b1, a1, /*residual=*/nullptr, xbuf);
    // layer 2: out = prelu(conv(x, W2) + b2 + feats)
    sparse_conv_kernel<<<grid, THREADS, SMEM_BYTES>>>(
        xbuf, nbr, msk, W2, b2, a2, /*residual=*/feats, out);
}